// round 17
// baseline (speedup 1.0000x reference)
#include <cuda_runtime.h>
#include <cstdint>

// ---------------------------------------------------------------------------
// SkinDeformNet — single fused kernel, ONE barrier.
// Pre-barrier (low regs, all overlapped): cp.async streams ws into smem;
//   every warp computes the rig (Rodrigues + shuffle kinematic chain) for its
//   self-sampled batch (warps 0-6: lane-0 point's batch; warp 7: lane-31's),
//   storing A12 into smem slot (batch & 3) — no blo needed, no pre-rig sync.
//   Warp 4 of blocks 0..B-1 emits Rs/Jt for batch = blockIdx.x instead.
// Post-barrier: R6 hot loop — w[24] from padded smem (conflict-free LDS.128),
//   A12 broadcast from smem slot (b & 3), row 3 of T constant, f32x2 FMA.
// ---------------------------------------------------------------------------

#define MAX_B  64
#define PTS_BLOCK 256
#define WROW 112u                    // 28 floats per ws row (4-phase LDS.128)

typedef unsigned long long ull;

__device__ const int c_par[24]   = {-1,0,0,0,1,2,3,4,5,6,7,8,9,9,9,12,13,14,16,17,18,19,20,21};
__device__ const int c_depth[24] = { 0,1,1,1,2,2,2,3,3,3,4,4,4,4,4, 5, 5, 5, 6, 6, 7, 7, 8, 8};

__device__ __forceinline__ ull fma2(ull a, ull b, ull c)
{
    ull d;
    asm("fma.rn.f32x2 %0, %1, %2, %3;" : "=l"(d) : "l"(a), "l"(b), "l"(c));
    return d;
}

__device__ __forceinline__ ull pack2(float v)
{
    ull d;
    asm("mov.b64 %0, {%1, %2};" : "=l"(d) : "f"(v), "f"(v));
    return d;
}

// Warp-cooperative rig for batch q (lane j = joint j, shuffle chain).
// Writes A12 into sA slot (q & 3) when fillSlot; writes Rs/Jt when writeOut.
__device__ __forceinline__ void rig_warp(
    int q, int lane,
    const float* __restrict__ Js, const float* __restrict__ poses,
    ull* __restrict__ sA, bool fillSlot,
    float* __restrict__ outRs, float* __restrict__ outJt, bool writeOut)
{
    const int jc = (lane < 24) ? lane : 0;

    const float rx = __ldg(poses + q*72 + jc*3 + 0);
    const float ry = __ldg(poses + q*72 + jc*3 + 1);
    const float rz = __ldg(poses + q*72 + jc*3 + 2);
    const float Jx = __ldg(Js + q*72 + jc*3 + 0);
    const float Jy = __ldg(Js + q*72 + jc*3 + 1);
    const float Jz = __ldg(Js + q*72 + jc*3 + 2);

    const float ang = sqrtf(rx*rx + ry*ry + rz*rz) + 1e-8f;
    const float inv = 1.0f / ang;
    const float x = rx*inv, y = ry*inv, z = rz*inv;
    const float s = sinf(ang), c = cosf(ang);
    const float o = 1.0f - c;
    const float R0 = 1.0f - o*(y*y + z*z);
    const float R1 = -s*z + o*(x*y);
    const float R2 =  s*y + o*(x*z);
    const float R3 =  s*z + o*(x*y);
    const float R4 = 1.0f - o*(x*x + z*z);
    const float R5 = -s*x + o*(y*z);
    const float R6 = -s*y + o*(x*z);
    const float R7 =  s*x + o*(y*z);
    const float R8 = 1.0f - o*(x*x + y*y);

    const int par  = (lane < 24) ? c_par[jc]   : 0;
    const int dep  = (lane < 24) ? c_depth[jc] : -1;
    const int psrc = (par < 0) ? 0 : par;

    const float pJx = __shfl_sync(0xFFFFFFFFu, Jx, psrc);
    const float pJy = __shfl_sync(0xFFFFFFFFu, Jy, psrc);
    const float pJz = __shfl_sync(0xFFFFFFFFu, Jz, psrc);
    const float tx = Jx - pJx, ty = Jy - pJy, tz = Jz - pJz;

    float res[12];
    res[0] = R0; res[1] = R1; res[2]  = R2; res[3]  = Jx;
    res[4] = R3; res[5] = R4; res[6]  = R5; res[7]  = Jy;
    res[8] = R6; res[9] = R7; res[10] = R8; res[11] = Jz;

    #pragma unroll
    for (int lv = 1; lv <= 8; lv++) {
        float pr[12];
        #pragma unroll
        for (int i = 0; i < 12; i++)
            pr[i] = __shfl_sync(0xFFFFFFFFu, res[i], psrc);
        if (dep == lv) {
            #pragma unroll
            for (int r = 0; r < 3; r++) {
                float p0 = pr[r*4+0], p1 = pr[r*4+1], p2 = pr[r*4+2], p3 = pr[r*4+3];
                res[r*4+0] = p0*R0 + p1*R3 + p2*R6;
                res[r*4+1] = p0*R1 + p1*R4 + p2*R7;
                res[r*4+2] = p0*R2 + p1*R5 + p2*R8;
                res[r*4+3] = p0*tx + p1*ty + p2*tz + p3;
            }
        }
    }

    if (lane < 24) {
        if (writeOut) {
            float* Rp = outRs + q*216 + lane*9;
            Rp[0]=R0; Rp[1]=R1; Rp[2]=R2; Rp[3]=R3; Rp[4]=R4;
            Rp[5]=R5; Rp[6]=R6; Rp[7]=R7; Rp[8]=R8;
            float* Jp = outJt + q*72 + lane*3;
            Jp[0] = res[3]; Jp[1] = res[7]; Jp[2] = res[11];
        }
        if (fillSlot) {
            const float tt = res[0]*Jx + res[1]*Jy + res[2]*Jz;
            const float tu = res[4]*Jx + res[5]*Jy + res[6]*Jz;
            const float tv = res[8]*Jx + res[9]*Jy + res[10]*Jz;
            float* slot = reinterpret_cast<float*>(sA + (size_t)(q & 3) * 144);
            float4* Ap = reinterpret_cast<float4*>(slot + lane*12);
            Ap[0] = make_float4(res[0], res[1], res[2],  res[3]  - tt);
            Ap[1] = make_float4(res[4], res[5], res[6],  res[7]  - tu);
            Ap[2] = make_float4(res[8], res[9], res[10], res[11] - tv);
        }
    }
}

// ============================= fused kernel ================================
__global__ void __launch_bounds__(PTS_BLOCK, 4)
skin_kernel(const float* __restrict__ ps,
            const float* __restrict__ Js,
            const float* __restrict__ ws,
            const float* __restrict__ poses,
            const void*  __restrict__ batch_raw,
            float* __restrict__ outP,
            float* __restrict__ outT,
            float* __restrict__ outRs,
            float* __restrict__ outJt,
            int N, int B)
{
    __shared__ __align__(16) char sW[PTS_BLOCK * WROW];  // 28672 B raw ws
    __shared__ __align__(16) ull  sA[4 * 144];           //  4608 B A12 slots

    const int tid  = threadIdx.x;
    const int lane = tid & 31;
    const int wid  = tid >> 5;
    const int base = blockIdx.x * PTS_BLOCK;
    const int n    = base + tid;
    const int nc   = (n < N) ? n : (N - 1);

    uint32_t sWb;
    asm("{ .reg .u64 t; cvta.to.shared.u64 t, %1; cvt.u32.u64 %0, t; }"
        : "=r"(sWb) : "l"(sW));

    const int*       b32 = (const int*)batch_raw;
    const long long* b64 = (const long long*)batch_raw;

    // dtype probe (warp-uniform, L2-hot): batch sorted, max = B-1 > 0. If
    // int64, the last 32-bit word is a zero high-half; if int32, it's B-1.
    const bool is64 = (__ldg(b32 + (N - 1)) == 0);
    const int  b    = is64 ? (int)__ldg(b64 + nc) : __ldg(b32 + nc);

    // ---- cp.async ws -> sW (RF-bypass; overlaps rig entirely) ----
    {
        const char* gsrc = (const char*)ws + (size_t)base * 96;
        const int maxi = (N - base) * 6;         // valid float4 chunks
        #pragma unroll
        for (int it = 0; it < 6; it++) {
            int i  = it * PTS_BLOCK + tid;       // 0..1535
            int ic = (i < maxi) ? i : (maxi - 1);
            uint32_t dst = sWb + (uint32_t)(i / 6) * WROW + (uint32_t)(i % 6) * 16u;
            asm volatile("cp.async.ca.shared.global [%0], [%1], 16;"
                         :: "r"(dst), "l"(gsrc + (size_t)ic * 16) : "memory");
        }
        asm volatile("cp.async.commit_group;" ::: "memory");
    }

    // prefetch ps (overlaps everything)
    const float px = __ldg(ps + (size_t)nc*3 + 0);
    const float py = __ldg(ps + (size_t)nc*3 + 1);
    const float pz = __ldg(ps + (size_t)nc*3 + 2);

    // ---- pre-barrier rig: self-sampled batch per warp, slot = batch & 3 ----
    // warps 0-6 sample lane 0 (covers window-low batch incl. warp 0 = blo);
    // warp 7 samples lane 31 (covers window-high batch even if its run < 32).
    {
        const int bw = __shfl_sync(0xFFFFFFFFu, b, (wid == 7) ? 31 : 0);
        if (wid == 4 && blockIdx.x < B) {
            // Rs/Jt emitter for batch = blockIdx.x (slot duty covered by others)
            rig_warp(blockIdx.x, lane, Js, poses, sA, false, outRs, outJt, true);
        } else {
            rig_warp(bw, lane, Js, poses, sA, true, outRs, outJt, false);
        }
    }

    asm volatile("cp.async.wait_group 0;" ::: "memory");
    __syncthreads();

    if (n >= N) return;

    // ---- hot loop: w[24] from padded smem (conflict-free LDS.128) ----
    float w[24];
    {
        const uint32_t wr = sWb + (uint32_t)tid * WROW;
        #pragma unroll
        for (int i = 0; i < 6; i++) {
            asm("ld.shared.v4.f32 {%0,%1,%2,%3}, [%4];"
                : "=f"(w[i*4+0]), "=f"(w[i*4+1]), "=f"(w[i*4+2]), "=f"(w[i*4+3])
                : "r"(wr + (uint32_t)i * 16u));
        }
    }

    ull acc[6];
    #pragma unroll
    for (int i = 0; i < 6; i++) acc[i] = 0ull;

    const ulonglong2* Ap =
        reinterpret_cast<const ulonglong2*>(sA + (size_t)(b & 3) * 144);
    #pragma unroll
    for (int k = 0; k < 24; k++) {
        ulonglong2 p0 = Ap[k*3 + 0];
        ulonglong2 p1 = Ap[k*3 + 1];
        ulonglong2 p2 = Ap[k*3 + 2];
        ull ww = pack2(w[k]);
        acc[0] = fma2(ww, p0.x, acc[0]);
        acc[1] = fma2(ww, p0.y, acc[1]);
        acc[2] = fma2(ww, p1.x, acc[2]);
        acc[3] = fma2(ww, p1.y, acc[3]);
        acc[4] = fma2(ww, p2.x, acc[4]);
        acc[5] = fma2(ww, p2.y, acc[5]);
    }

    float t[12];
    #pragma unroll
    for (int i = 0; i < 6; i++)
        asm("mov.b64 {%0, %1}, %2;" : "=f"(t[2*i]), "=f"(t[2*i+1]) : "l"(acc[i]));

    float4* Tp = reinterpret_cast<float4*>(outT + (size_t)n * 16);
    Tp[0] = make_float4(t[0], t[1], t[2],  t[3]);
    Tp[1] = make_float4(t[4], t[5], t[6],  t[7]);
    Tp[2] = make_float4(t[8], t[9], t[10], t[11]);
    Tp[3] = make_float4(0.0f, 0.0f, 0.0f,  1.0f);

    outP[(size_t)n*3 + 0] = t[0]*px + t[1]*py + t[2] *pz + t[3];
    outP[(size_t)n*3 + 1] = t[4]*px + t[5]*py + t[6] *pz + t[7];
    outP[(size_t)n*3 + 2] = t[8]*px + t[9]*py + t[10]*pz + t[11];
}

// =============================== launch ====================================
extern "C" void kernel_launch(void* const* d_in, const int* in_sizes, int n_in,
                              void* d_out, int out_size)
{
    const float* ps    = (const float*)d_in[0];
    const float* Js    = (const float*)d_in[1];
    const float* ws    = (const float*)d_in[2];
    const float* poses = (const float*)d_in[3];
    const void*  batch = d_in[4];

    const int N = in_sizes[0] / 3;
    int B = in_sizes[3] / 72;
    if (B > MAX_B) B = MAX_B;

    float* out   = (float*)d_out;
    float* outP  = out;                                  // N*3
    float* outT  = outP + (size_t)N * 3;                 // N*16
    float* outRs = outT + (size_t)N * 16;                // B*216
    float* outJt = outRs + (size_t)B * 216;              // B*72

    const int blocks = (N + PTS_BLOCK - 1) / PTS_BLOCK;
    skin_kernel<<<blocks, PTS_BLOCK>>>(ps, Js, ws, poses, batch,
                                       outP, outT, outRs, outJt, N, B);
}